// round 9
// baseline (speedup 1.0000x reference)
#include <cuda_runtime.h>
#include <cuda_fp16.h>

#define HID 5
#define HDIM 2048
#define BSZ 16384

__device__ int g_lengths[BSZ];

// ---------------------------------------------------------------------------
// Kernel 1: per-row nonzero count (ragged length, matches reference mask)
// ---------------------------------------------------------------------------
__global__ void len_kernel(const float* __restrict__ x) {
    int b = blockIdx.x;
    const float4* row = reinterpret_cast<const float4*>(x + (size_t)b * HDIM);
    int tid = threadIdx.x;
    int cnt = 0;
#pragma unroll
    for (int i = 0; i < 2; i++) {
        float4 v = row[tid + i * 256];
        cnt += (v.x != 0.f) + (v.y != 0.f) + (v.z != 0.f) + (v.w != 0.f);
    }
    __shared__ int s[8];
#pragma unroll
    for (int o = 16; o > 0; o >>= 1) cnt += __shfl_down_sync(0xffffffffu, cnt, o);
    if ((tid & 31) == 0) s[tid >> 5] = cnt;
    __syncthreads();
    if (tid < 8) {
        int v = s[tid];
#pragma unroll
        for (int o = 4; o > 0; o >>= 1) v += __shfl_down_sync(0xffu, v, o);
        if (tid == 0) g_lengths[b] = v;
    }
}

// ---------------------------------------------------------------------------
// helpers
// ---------------------------------------------------------------------------
__device__ __forceinline__ float fast_tanh(float v) {
    float r; asm("tanh.approx.f32 %0, %1;" : "=f"(r) : "f"(v)); return r;
}
__device__ __forceinline__ unsigned tanh2u(unsigned u) {
    unsigned r; asm("tanh.approx.f16x2 %0, %1;" : "=r"(r) : "r"(u)); return r;
}
// pack two f32 into f16x2: lo -> low half, hi -> high half
__device__ __forceinline__ unsigned pack2(float lo, float hi) {
    unsigned r; asm("cvt.rn.f16x2.f32 %0, %1, %2;" : "=r"(r) : "f"(hi), "f"(lo));
    return r;
}
__device__ __forceinline__ float lo2f(unsigned u) {
    return __half2float(__ushort_as_half((unsigned short)(u & 0xffffu)));
}
__device__ __forceinline__ float hi2f(unsigned u) {
    return __half2float(__ushort_as_half((unsigned short)(u >> 16)));
}

// D = A(16x8,f16,row) * B(8x8,f16,col) + C(f32)   — bias C replicated rows
__device__ __forceinline__ void mma8(float* d, unsigned a0, unsigned a1,
                                     unsigned b, float c0, float c1) {
    asm("mma.sync.aligned.m16n8k8.row.col.f32.f16.f16.f32 "
        "{%0,%1,%2,%3}, {%4,%5}, {%6}, {%7,%8,%9,%10};"
        : "=f"(d[0]), "=f"(d[1]), "=f"(d[2]), "=f"(d[3])
        : "r"(a0), "r"(a1), "r"(b), "f"(c0), "f"(c1), "f"(c0), "f"(c1));
}

// one LSTM unit update; i,f,o preactivations arrive prescaled by 0.5
__device__ __forceinline__ void unit_update(float fi, float ff, float fgv, float fo,
                                            float& c, float& h, bool upd) {
    const unsigned tif = tanh2u(pack2(fi, ff));   // {tanh(.5zi), tanh(.5zf)}
    const unsigned tgo = tanh2u(pack2(fgv, fo));  // {tanh(zg),   tanh(.5zo)}
    const float ig = fmaf(lo2f(tif), 0.5f, 0.5f);
    const float fg = fmaf(hi2f(tif), 0.5f, 0.5f);
    const float tg = lo2f(tgo);
    const float og = fmaf(hi2f(tgo), 0.5f, 0.5f);
    const float cn = fmaf(fg, c, ig * tg);
    const float hn = og * fast_tanh(cn);
    c = upd ? cn : c;
    h = upd ? hn : h;
}

// ---------------------------------------------------------------------------
// LSTM: warp = 32 sequences. gates[32,32cols] = [h|x|0]·B + bias via 8 HMMA.
// Column permutation (4 n-tiles of 8): thread t=lane&3 owns units 2t,2t+1
// completely, and its A cols {2t,2t+1} are exactly those h's -> no shuffles.
// W_hh row ids: i=u, f=5+u, g=10+u, o=15+u;  i/f/o rows prescaled by 0.5.
// ---------------------------------------------------------------------------
__global__ void __launch_bounds__(64, 1) lstm_kernel(
    const float* __restrict__ x,
    const float* __restrict__ W_ih,
    const float* __restrict__ W_hh,
    const float* __restrict__ b_ih,
    const float* __restrict__ b_hh,
    float* __restrict__ out)
{
    const int lane = threadIdx.x & 31;
    const int warp = (blockIdx.x * blockDim.x + threadIdx.x) >> 5;
    const int g  = lane >> 2;   // row-group (A/D) and n-index (B)
    const int tq = lane & 3;    // D col-pair / B k-pair
    const int seqbase = warp * 32;

    int rows[4];
#pragma unroll
    for (int m = 0; m < 2; m++) {
        rows[2 * m]     = seqbase + m * 16 + g;
        rows[2 * m + 1] = seqbase + m * 16 + g + 8;
    }

    const int gmap[4][8] = {
        { 0,  5,  2,  7,  4,  9, -1, -1},   // i0,f0,i2,f2,i4,f4
        {10, 15, 12, 17, 14, 19, -1, -1},   // g0,o0,g2,o2,g4,o4
        { 1,  6,  3,  8, -1, -1, -1, -1},   // i1,f1,i3,f3
        {11, 16, 13, 18, -1, -1, -1, -1}};  // g1,o1,g3,o3

    // B fragments: B[k][n], k=0..4 -> Whh row cols, k=5 -> Wih, k=6,7 -> 0
    unsigned bfrag[4];
    float bias0[4], bias1[4];
#pragma unroll
    for (int tt = 0; tt < 4; tt++) {
        const int rn = gmap[tt][g];                    // my B n-column's gate row
        const float sn = (rn < 0) ? 0.f : ((rn >= 10 && rn < 15) ? 1.f : 0.5f);
        float v0 = 0.f, v1 = 0.f;
        const int k0 = 2 * tq, k1 = 2 * tq + 1;
        if (rn >= 0) {
            v0 = (k0 < HID) ? sn * W_hh[rn * HID + k0] : (k0 == HID ? sn * W_ih[rn] : 0.f);
            v1 = (k1 < HID) ? sn * W_hh[rn * HID + k1] : (k1 == HID ? sn * W_ih[rn] : 0.f);
        }
        bfrag[tt] = pack2(v0, v1);

        const int rc0 = gmap[tt][2 * tq], rc1 = gmap[tt][2 * tq + 1];
        bias0[tt] = (rc0 < 0) ? 0.f :
            ((rc0 >= 10 && rc0 < 15) ? 1.f : 0.5f) * (b_ih[rc0] + b_hh[rc0]);
        bias1[tt] = (rc1 < 0) ? 0.f :
            ((rc1 >= 10 && rc1 < 15) ? 1.f : 0.5f) * (b_ih[rc1] + b_hh[rc1]);
    }

    int len[4], lmax = 0;
#pragma unroll
    for (int r = 0; r < 4; r++) { len[r] = g_lengths[rows[r]]; lmax = max(lmax, len[r]); }
    lmax = __reduce_max_sync(0xffffffffu, lmax);

    float hA[4] = {0.f, 0.f, 0.f, 0.f}, hB[4] = {0.f, 0.f, 0.f, 0.f};
    float cA[4] = {0.f, 0.f, 0.f, 0.f}, cB[4] = {0.f, 0.f, 0.f, 0.f};

    float4 xa[4];
#pragma unroll
    for (int r = 0; r < 4; r++)
        xa[r] = *reinterpret_cast<const float4*>(x + (size_t)rows[r] * HDIM);

    for (int t0 = 0; t0 < lmax; t0 += 4) {
        float4 xn[4];
        const int nt = t0 + 4;
#pragma unroll
        for (int r = 0; r < 4; r++)
            xn[r] = (nt < HDIM)
                ? *reinterpret_cast<const float4*>(x + (size_t)rows[r] * HDIM + nt)
                : xa[r];

        float xs[4][4];
#pragma unroll
        for (int r = 0; r < 4; r++) {
            xs[r][0] = xa[r].x; xs[r][1] = xa[r].y;
            xs[r][2] = xa[r].z; xs[r][3] = xa[r].w;
        }

#pragma unroll
        for (int s = 0; s < 4; s++) {
            const int t = t0 + s;

            // A fragments: per row r, cols {2tq,2tq+1} = {hA, hB} (tq==2: {h4, x})
            unsigned afr[4];
#pragma unroll
            for (int r = 0; r < 4; r++) {
                const float pb = (tq == 2) ? xs[r][s] : hB[r];
                afr[r] = pack2(hA[r], pb);
            }

            float d[2][4][4];
#pragma unroll
            for (int m = 0; m < 2; m++)
#pragma unroll
                for (int tt = 0; tt < 4; tt++)
                    mma8(d[m][tt], afr[2 * m], afr[2 * m + 1],
                         bfrag[tt], bias0[tt], bias1[tt]);

            // epilogue: rows 0..3 (m-tile m, sub-row rr), units A (tiles0/1), B (tiles2/3)
#pragma unroll
            for (int m = 0; m < 2; m++)
#pragma unroll
                for (int rr = 0; rr < 2; rr++) {
                    const int r = 2 * m + rr;
                    const bool upd = (t < len[r]);
                    unit_update(d[m][0][2 * rr], d[m][0][2 * rr + 1],
                                d[m][1][2 * rr], d[m][1][2 * rr + 1],
                                cA[r], hA[r], upd);
                    unit_update(d[m][2][2 * rr], d[m][2][2 * rr + 1],
                                d[m][3][2 * rr], d[m][3][2 * rr + 1],
                                cB[r], hB[r], upd);
                }
        }
#pragma unroll
        for (int r = 0; r < 4; r++) xa[r] = xn[r];
    }

    const int uA = 2 * tq, uB = 2 * tq + 1;
#pragma unroll
    for (int r = 0; r < 4; r++) {
        if (uA < HID) out[rows[r] * HID + uA] = hA[r];
        if (uB < HID) out[rows[r] * HID + uB] = hB[r];
    }
}

// ---------------------------------------------------------------------------
extern "C" void kernel_launch(void* const* d_in, const int* in_sizes, int n_in,
                              void* d_out, int out_size) {
    const float* x    = (const float*)d_in[0];
    const float* W_ih = (const float*)d_in[1];
    const float* W_hh = (const float*)d_in[2];
    const float* b_ih = (const float*)d_in[3];
    const float* b_hh = (const float*)d_in[4];
    float* out = (float*)d_out;

    len_kernel<<<BSZ, 256>>>(x);
    lstm_kernel<<<BSZ / 64, 64>>>(x, W_ih, W_hh, b_ih, b_hh, out);
}

// round 10
// speedup vs baseline: 1.5842x; 1.5842x over previous
#include <cuda_runtime.h>
#include <cuda_fp16.h>

#define HID 5
#define HDIM 2048
#define BSZ 16384

__device__ int g_lengths[BSZ];

// ---------------------------------------------------------------------------
// Kernel 1: per-row nonzero count (ragged length, matches reference mask)
// ---------------------------------------------------------------------------
__global__ void len_kernel(const float* __restrict__ x) {
    int b = blockIdx.x;
    const float4* row = reinterpret_cast<const float4*>(x + (size_t)b * HDIM);
    int tid = threadIdx.x;
    int cnt = 0;
#pragma unroll
    for (int i = 0; i < 2; i++) {
        float4 v = row[tid + i * 256];
        cnt += (v.x != 0.f) + (v.y != 0.f) + (v.z != 0.f) + (v.w != 0.f);
    }
    __shared__ int s[8];
#pragma unroll
    for (int o = 16; o > 0; o >>= 1) cnt += __shfl_down_sync(0xffffffffu, cnt, o);
    if ((tid & 31) == 0) s[tid >> 5] = cnt;
    __syncthreads();
    if (tid < 8) {
        int v = s[tid];
#pragma unroll
        for (int o = 4; o > 0; o >>= 1) v += __shfl_down_sync(0xffu, v, o);
        if (tid == 0) g_lengths[b] = v;
    }
}

// ---------------------------------------------------------------------------
// math helpers
// ---------------------------------------------------------------------------
__device__ __forceinline__ float fast_tanh(float v) {
    float r; asm("tanh.approx.f32 %0, %1;" : "=f"(r) : "f"(v)); return r;
}
__device__ __forceinline__ __half2 tanh2(__half2 v) {
    unsigned u = *reinterpret_cast<unsigned*>(&v), r;
    asm("tanh.approx.f16x2 %0, %1;" : "=r"(r) : "r"(u));
    return *reinterpret_cast<__half2*>(&r);
}

// ---------------------------------------------------------------------------
// LSTM: 1 thread / sequence.
// Gate GEMV in fp16 HFMA2. Pair layout unit-major:
//   P_u = {0.5*i_u, 0.5*f_u},  Q_u = {0.5*o_u, g_u}.
// One tanh2 per pair: tanh2(P) -> both sigmoid cores; tanh2(Q) -> {sig core
// of o, tanh(g)} — g's tanh comes from the SAME f16x2 op (no fp32 redo).
// cn, tanh(cn), h update in fp32.  MUFU/step: 5+5+5 = 15 (was 20).
// ---------------------------------------------------------------------------
struct State {
    __half2 h2[HID];   // {h_j, h_j} fp16 for the GEMV
    float   c[HID];    // fp32 cell state
    float   h[HID];    // fp32 hidden (output path)
};

__device__ __forceinline__ void lstm_step(State& st, float xv,
    const __half2* __restrict__ wihP, const __half2* __restrict__ wihQ,
    const __half2* __restrict__ bsP,  const __half2* __restrict__ bsQ,
    const __half2 (*whhP)[HID], const __half2 (*whhQ)[HID])
{
    const __half2 x2 = __float2half2_rn(xv);
    __half2 aP[HID], aQ[HID];
#pragma unroll
    for (int u = 0; u < HID; u++) {
        __half2 a = __hfma2(x2, wihP[u], bsP[u]);
        __half2 b = __hfma2(x2, wihQ[u], bsQ[u]);
#pragma unroll
        for (int j = 0; j < HID; j++) {
            a = __hfma2(st.h2[j], whhP[u][j], a);
            b = __hfma2(st.h2[j], whhQ[u][j], b);
        }
        aP[u] = a; aQ[u] = b;
    }
    const __half2 h05 = __float2half2_rn(0.5f);
#pragma unroll
    for (int u = 0; u < HID; u++) {
        const __half2 tP = tanh2(aP[u]);                 // {t(.5zi), t(.5zf)}
        const __half2 tQ = tanh2(aQ[u]);                 // {t(.5zo), t(zg)}
        const __half2 sP = __hfma2(tP, h05, h05);        // {ig, fg}
        const float ig = __low2float(sP);
        const float fg = __high2float(sP);
        const float og = fmaf(__low2float(tQ), 0.5f, 0.5f);
        const float tg = __high2float(tQ);               // f16 tanh(g) — free
        const float cn = fmaf(fg, st.c[u], ig * tg);
        st.c[u] = cn;
        const float hn = og * fast_tanh(cn);             // fp32 tanh(c)
        st.h[u]  = hn;
        st.h2[u] = __float2half2_rn(hn);                 // ready for next GEMV
    }
}

__global__ void __launch_bounds__(64, 1) lstm_kernel(
    const float* __restrict__ x,
    const float* __restrict__ W_ih,
    const float* __restrict__ W_hh,
    const float* __restrict__ b_ih,
    const float* __restrict__ b_hh,
    float* __restrict__ out)
{
    int b = blockIdx.x * blockDim.x + threadIdx.x;

    // gate rows: i:0-4  f:5-9  g:10-14  o:15-19
    __half2 wihP[HID], wihQ[HID], bsP[HID], bsQ[HID];
    __half2 whhP[HID][HID], whhQ[HID][HID];
#pragma unroll
    for (int u = 0; u < HID; u++) {
        const int ri = u, rf = HID + u, rg = 2 * HID + u, ro = 3 * HID + u;
        wihP[u] = __floats2half2_rn(0.5f * W_ih[ri], 0.5f * W_ih[rf]);
        wihQ[u] = __floats2half2_rn(0.5f * W_ih[ro], W_ih[rg]);
        bsP[u]  = __floats2half2_rn(0.5f * (b_ih[ri] + b_hh[ri]),
                                    0.5f * (b_ih[rf] + b_hh[rf]));
        bsQ[u]  = __floats2half2_rn(0.5f * (b_ih[ro] + b_hh[ro]),
                                    (b_ih[rg] + b_hh[rg]));
#pragma unroll
        for (int j = 0; j < HID; j++) {
            whhP[u][j] = __floats2half2_rn(0.5f * W_hh[ri * HID + j],
                                           0.5f * W_hh[rf * HID + j]);
            whhQ[u][j] = __floats2half2_rn(0.5f * W_hh[ro * HID + j],
                                           W_hh[rg * HID + j]);
        }
    }

    const int len = g_lengths[b];
    const float* row = x + (size_t)b * HDIM;

    State st;
#pragma unroll
    for (int u = 0; u < HID; u++) {
        st.h2[u] = __float2half2_rn(0.f);
        st.c[u] = 0.f;
        st.h[u] = 0.f;
    }

    float4 a0 = make_float4(0.f, 0.f, 0.f, 0.f);
    if (len > 0) a0 = *reinterpret_cast<const float4*>(row);

    for (int t0 = 0; t0 < len; t0 += 4) {
        // prefetch next 4 timesteps (HDIM multiple of 4)
        float4 nx = a0;
        const int nt = t0 + 4;
        if (nt < HDIM) nx = *reinterpret_cast<const float4*>(row + nt);

        const int nrem = len - t0;
        if (nrem >= 4) {
            lstm_step(st, a0.x, wihP, wihQ, bsP, bsQ, whhP, whhQ);
            lstm_step(st, a0.y, wihP, wihQ, bsP, bsQ, whhP, whhQ);
            lstm_step(st, a0.z, wihP, wihQ, bsP, bsQ, whhP, whhQ);
            lstm_step(st, a0.w, wihP, wihQ, bsP, bsQ, whhP, whhQ);
        } else {
            float xs[4] = {a0.x, a0.y, a0.z, a0.w};
#pragma unroll
            for (int k = 0; k < 4; k++)
                if (k < nrem)
                    lstm_step(st, xs[k], wihP, wihQ, bsP, bsQ, whhP, whhQ);
        }
        a0 = nx;
    }

#pragma unroll
    for (int u = 0; u < HID; u++) out[b * HID + u] = st.h[u];
}

// ---------------------------------------------------------------------------
extern "C" void kernel_launch(void* const* d_in, const int* in_sizes, int n_in,
                              void* d_out, int out_size) {
    const float* x    = (const float*)d_in[0];
    const float* W_ih = (const float*)d_in[1];
    const float* W_hh = (const float*)d_in[2];
    const float* b_ih = (const float*)d_in[3];
    const float* b_hh = (const float*)d_in[4];
    float* out = (float*)d_out;

    len_kernel<<<BSZ, 256>>>(x);
    lstm_kernel<<<BSZ / 64, 64>>>(x, W_ih, W_hh, b_ih, b_hh, out);
}